// round 5
// baseline (speedup 1.0000x reference)
#include <cuda_runtime.h>
#include <cstdint>
#include <cstddef>

#define BATCH 256
#define SEQ   512
#define INDIM 32
#define H0 64
#define H1 128
#define H2 256

typedef unsigned long long ull;

__device__ float g_pre [(size_t)BATCH * SEQ * 4 * H2];
__device__ float g_x1  [(size_t)BATCH * SEQ * H0];
__device__ float g_x2  [(size_t)BATCH * SEQ * H1];
__device__ float g_x3  [(size_t)BATCH * SEQ * H2];

__device__ __forceinline__ float sigf(float x)  { return 1.f / (1.f + __expf(-x)); }
__device__ __forceinline__ float tanhfast(float x) { return 2.f / (1.f + __expf(-2.f * x)) - 1.f; }

__device__ __forceinline__ void ffma2(ull& d, ull a, ull b) {
    asm("fma.rn.f32x2 %0, %1, %2, %3;" : "=l"(d) : "l"(a), "l"(b), "l"(d));
}
__device__ __forceinline__ ull add2(ull a, ull b) {
    ull r; asm("add.rn.f32x2 %0, %1, %2;" : "=l"(r) : "l"(a), "l"(b)); return r;
}
__device__ __forceinline__ ull dup2(float w) {
    ull r; asm("mov.b64 %0, {%1, %1};" : "=l"(r) : "f"(w)); return r;
}
__device__ __forceinline__ ull pack2(float x, float y) {
    ull r; asm("mov.b64 %0, {%1, %2};" : "=l"(r) : "f"(x), "f"(y)); return r;
}
__device__ __forceinline__ void unpk(ull v, float& lo, float& hi) {
    asm("mov.b64 {%0, %1}, %2;" : "=f"(lo), "=f"(hi) : "l"(v));
}
__device__ __forceinline__ uint32_t cvta_s(const void* p) {
    return (uint32_t)__cvta_generic_to_shared(p);
}
__device__ __forceinline__ ull lds64(uint32_t a) {
    ull v; asm volatile("ld.shared.b64 %0, [%1];" : "=l"(v) : "r"(a)); return v;
}
__device__ __forceinline__ void lds2x64(uint32_t a, ull& x, ull& y) {
    asm volatile("ld.shared.v2.u64 {%0, %1}, [%2];" : "=l"(x), "=l"(y) : "r"(a));
}
__device__ __forceinline__ void sts64(uint32_t a, ull v) {
    asm volatile("st.shared.b64 [%0], %1;" :: "r"(a), "l"(v));
}
__device__ __forceinline__ void stc64(uint32_t la, unsigned rank, ull v) {
    uint32_t ra;
    asm("mapa.shared::cluster.u32 %0, %1, %2;" : "=r"(ra) : "r"(la), "r"(rank));
    asm volatile("st.shared::cluster.b64 [%0], %1;" :: "r"(ra), "l"(v) : "memory");
}
__device__ __forceinline__ void cluster_sync_() {
    asm volatile("barrier.cluster.arrive.aligned;" ::: "memory");
    asm volatile("barrier.cluster.wait.aligned;" ::: "memory");
}

// ---------------- input GEMM (unchanged from R2) ----------------
template <int K, int N>
__global__ void __launch_bounds__(256) gemm_pre_kernel(
    const float* __restrict__ X, const float* __restrict__ W,
    const float* __restrict__ bih, const float* __restrict__ bhh,
    float* __restrict__ C)
{
    constexpr int BM = 128, BN = 64, BK = 32;
    __shared__ float Xs[BK * BM];
    __shared__ float Wt[BK * BN];
    const int m0 = blockIdx.x * BM, n0 = blockIdx.y * BN, tid = threadIdx.x;

    float acc[8][4];
#pragma unroll
    for (int i = 0; i < 8; i++)
#pragma unroll
        for (int j = 0; j < 4; j++) acc[i][j] = 0.f;

    const int tm = (tid >> 4) << 3;
    const int tn = (tid & 15) << 2;

    for (int k0 = 0; k0 < K; k0 += BK) {
#pragma unroll
        for (int i = 0; i < 4; i++) {
            int f4 = tid + i * 256, row = f4 >> 3, kk = (f4 & 7) << 2;
            float4 v = *reinterpret_cast<const float4*>(&X[(size_t)(m0 + row) * K + k0 + kk]);
            Xs[(kk + 0) * BM + row] = v.x; Xs[(kk + 1) * BM + row] = v.y;
            Xs[(kk + 2) * BM + row] = v.z; Xs[(kk + 3) * BM + row] = v.w;
        }
#pragma unroll
        for (int i = 0; i < 2; i++) {
            int f4 = tid + i * 256, row = f4 >> 3, kk = (f4 & 7) << 2;
            float4 v = *reinterpret_cast<const float4*>(&W[(size_t)(n0 + row) * K + k0 + kk]);
            Wt[(kk + 0) * BN + row] = v.x; Wt[(kk + 1) * BN + row] = v.y;
            Wt[(kk + 2) * BN + row] = v.z; Wt[(kk + 3) * BN + row] = v.w;
        }
        __syncthreads();
#pragma unroll
        for (int kk = 0; kk < BK; kk++) {
            float4 a0 = *reinterpret_cast<const float4*>(&Xs[kk * BM + tm]);
            float4 a1 = *reinterpret_cast<const float4*>(&Xs[kk * BM + tm + 4]);
            float4 b  = *reinterpret_cast<const float4*>(&Wt[kk * BN + tn]);
            float a[8] = {a0.x, a0.y, a0.z, a0.w, a1.x, a1.y, a1.z, a1.w};
            float bb[4] = {b.x, b.y, b.z, b.w};
#pragma unroll
            for (int i = 0; i < 8; i++)
#pragma unroll
                for (int j = 0; j < 4; j++) acc[i][j] += a[i] * bb[j];
        }
        __syncthreads();
    }
    float bb4[4];
#pragma unroll
    for (int n = 0; n < 4; n++) bb4[n] = bih[n0 + tn + n] + bhh[n0 + tn + n];
#pragma unroll
    for (int i = 0; i < 8; i++) {
        float4 o = {acc[i][0] + bb4[0], acc[i][1] + bb4[1],
                    acc[i][2] + bb4[2], acc[i][3] + bb4[3]};
        *reinterpret_cast<float4*>(&C[(size_t)(m0 + tm + i) * N + n0 + tn]) = o;
    }
}

// ---------------- LSTM recurrence: 256 thr, K-split warps, f32x2 batch pairs ----
// thread(dot) = (j in JS, kh in KH); each (j,kh) accumulates all NB batches (BP
// pairs) over its K-range into f32x2 partials -> smem reduce -> thread(act) =
// (j, pr) finishes one batch pair (c in regs), pushes packed h to all G peers.
template <int H, int G, int NB, int KH>
__global__ void __launch_bounds__(256) lstm_recur_kernel(
    const float* __restrict__ pre, const float* __restrict__ Whh,
    float* __restrict__ xout)
{
    constexpr int JS = H / G;      // hidden units per CTA
    constexpr int BP = NB / 2;     // batch pairs
    constexpr int KR = H / KH;     // k per warp-group
    static_assert(JS * KH == 256, "map");

    extern __shared__ float sm[];
    float* Ws = sm;                         // [H][JS][4]
    float* hs = Ws + H * JS * 4;            // [2][H][NB]
    ull*   red = (ull*)(hs + 2 * H * NB);   // [KH][4][BP][JS]

    const int tid = threadIdx.x;
    const int j   = tid % JS;
    const int kh  = tid / JS;
    const int grp = (G > 1) ? (blockIdx.x / G) : blockIdx.x;
    const int sl  = (G > 1) ? (blockIdx.x % G) : 0;
    const int b0  = grp * NB;
    const int j0  = sl * JS;

    for (int gj = 0; gj < 4 * JS; gj++) {
        const int g = gj / JS, jj = gj % JS;
        const float* src = Whh + (size_t)(g * H + j0 + jj) * H;
        for (int k = tid; k < H; k += 256)
            Ws[(k * JS + jj) * 4 + g] = src[k];
    }
    for (int i = tid; i < 2 * H * NB; i += 256) hs[i] = 0.f;
    __syncthreads();
    if (G > 1) cluster_sync_();

    const uint32_t hsb  = cvta_s(hs);
    const uint32_t redb = cvta_s(red);
    const int kbeg = kh * KR;

    // activation identity
    const int pr = tid / JS;                 // pair index
    const bool ACT = (pr < BP);
    const float* pp0 = pre; const float* pp1 = pre;
    float* xo0 = xout; float* xo1 = xout;
    float pin[2][4];
    float c0 = 0.f, c1 = 0.f;
    if (ACT) {
        const int bA = b0 + 2 * pr;
        pp0 = pre + (size_t)bA * SEQ * (4 * H) + j0 + j;
        pp1 = pp0 + (size_t)SEQ * (4 * H);
        xo0 = xout + (size_t)bA * SEQ * H + j0 + j;
        xo1 = xo0 + (size_t)SEQ * H;
#pragma unroll
        for (int g = 0; g < 4; g++) {
            pin[0][g] = __ldcs(pp0 + g * H);
            pin[1][g] = __ldcs(pp1 + g * H);
        }
    }

    for (int t = 0; t < SEQ; t++) {
        const uint32_t hb = hsb + (uint32_t)((t & 1) * H * NB) * 4u;

        ull acc[4][BP];
#pragma unroll
        for (int g = 0; g < 4; g++)
#pragma unroll
            for (int p = 0; p < BP; p++) acc[g][p] = 0ull;

#pragma unroll 4
        for (int kk = 0; kk < KR; kk++) {
            const int k = kbeg + kk;
            float4 w4 = *reinterpret_cast<const float4*>(&Ws[(k * JS + j) * 4]);
            ull wd[4] = {dup2(w4.x), dup2(w4.y), dup2(w4.z), dup2(w4.w)};
            const uint32_t ha = hb + (uint32_t)(k * NB) * 4u;
            ull h2[BP];
#pragma unroll
            for (int p = 0; p < BP; p += 2) lds2x64(ha + p * 8u, h2[p], h2[p + 1]);
#pragma unroll
            for (int g = 0; g < 4; g++)
#pragma unroll
                for (int p = 0; p < BP; p++) ffma2(acc[g][p], h2[p], wd[g]);
        }
#pragma unroll
        for (int g = 0; g < 4; g++)
#pragma unroll
            for (int p = 0; p < BP; p++)
                sts64(redb + (uint32_t)(((kh * 4 + g) * BP + p) * JS + j) * 8u, acc[g][p]);
        __syncthreads();

        if (ACT) {
            // prefetch pre(t+1) early — consumed next step
            const int tn = (t + 1 < SEQ) ? t + 1 : t;
            float pn[2][4];
#pragma unroll
            for (int g = 0; g < 4; g++) {
                pn[0][g] = __ldcs(pp0 + (size_t)tn * 4 * H + g * H);
                pn[1][g] = __ldcs(pp1 + (size_t)tn * 4 * H + g * H);
            }
            float s0[4], s1[4];
#pragma unroll
            for (int g = 0; g < 4; g++) {
                ull v = lds64(redb + (uint32_t)((g * BP + pr) * JS + j) * 8u);
#pragma unroll
                for (int kp = 1; kp < KH; kp++)
                    v = add2(v, lds64(redb +
                        (uint32_t)(((kp * 4 + g) * BP + pr) * JS + j) * 8u));
                unpk(v, s0[g], s1[g]);
                s0[g] += pin[0][g];
                s1[g] += pin[1][g];
            }
            float h0, h1;
            {
                const float gi = sigf(s0[0]), gf = sigf(s0[1]);
                const float gg = tanhfast(s0[2]), go = sigf(s0[3]);
                c0 = gf * c0 + gi * gg;  h0 = go * tanhfast(c0);
            }
            {
                const float gi = sigf(s1[0]), gf = sigf(s1[1]);
                const float gg = tanhfast(s1[2]), go = sigf(s1[3]);
                c1 = gf * c1 + gi * gg;  h1 = go * tanhfast(c1);
            }
            xo0[(size_t)t * H] = h0;
            xo1[(size_t)t * H] = h1;

            const ull hp = pack2(h0, h1);
            const uint32_t la = hsb +
                (uint32_t)((((t + 1) & 1) * H + j0 + j) * NB + 2 * pr) * 4u;
            if (G == 1) {
                sts64(la, hp);
            } else {
#pragma unroll
                for (unsigned dst = 0; dst < G; dst++) stc64(la, dst, hp);
            }
#pragma unroll
            for (int g = 0; g < 4; g++) { pin[0][g] = pn[0][g]; pin[1][g] = pn[1][g]; }
        }

        if (G == 1) __syncthreads();
        else        cluster_sync_();
    }
}

// ---------------- final linear (OUT_DIM=1) + tanh ----------------
__global__ void __launch_bounds__(256) final_kernel(
    const float* __restrict__ x3, const float* __restrict__ Wl,
    const float* __restrict__ bl, float* __restrict__ out)
{
    int warp = (blockIdx.x * 256 + threadIdx.x) >> 5;
    int lane = threadIdx.x & 31;
    const float* xr = x3 + (size_t)warp * H2;
    float acc = 0.f;
#pragma unroll
    for (int i = 0; i < 8; i++) acc += xr[i * 32 + lane] * __ldg(&Wl[i * 32 + lane]);
#pragma unroll
    for (int off = 16; off; off >>= 1) acc += __shfl_xor_sync(0xffffffffu, acc, off);
    if (lane == 0) out[warp] = tanhf(acc + bl[0]);
}

// ---------------- launch ----------------
template <typename KernT>
static void launch_cluster(KernT kern, int grid, int G, int smem,
                           const float* pre, const float* Whh, float* xout)
{
    cudaLaunchConfig_t cfg = {};
    cfg.gridDim = dim3(grid, 1, 1);
    cfg.blockDim = dim3(256, 1, 1);
    cfg.dynamicSmemBytes = smem;
    cfg.stream = 0;
    cudaLaunchAttribute attr[1];
    attr[0].id = cudaLaunchAttributeClusterDimension;
    attr[0].val.clusterDim.x = G;
    attr[0].val.clusterDim.y = 1;
    attr[0].val.clusterDim.z = 1;
    cfg.attrs = attr;
    cfg.numAttrs = 1;
    cudaLaunchKernelEx(&cfg, kern, pre, Whh, xout);
}

extern "C" void kernel_launch(void* const* d_in, const int* in_sizes, int n_in,
                              void* d_out, int out_size)
{
    const float* noise = (const float*)d_in[0];
    const float* Wih0 = (const float*)d_in[1];
    const float* Whh0 = (const float*)d_in[2];
    const float* bih0 = (const float*)d_in[3];
    const float* bhh0 = (const float*)d_in[4];
    const float* Wih1 = (const float*)d_in[5];
    const float* Whh1 = (const float*)d_in[6];
    const float* bih1 = (const float*)d_in[7];
    const float* bhh1 = (const float*)d_in[8];
    const float* Wih2 = (const float*)d_in[9];
    const float* Whh2 = (const float*)d_in[10];
    const float* bih2 = (const float*)d_in[11];
    const float* bhh2 = (const float*)d_in[12];
    const float* Wl   = (const float*)d_in[13];
    const float* bl   = (const float*)d_in[14];
    float* out = (float*)d_out;

    float *pre, *x1, *x2, *x3;
    cudaGetSymbolAddress((void**)&pre, g_pre);
    cudaGetSymbolAddress((void**)&x1,  g_x1);
    cudaGetSymbolAddress((void**)&x2,  g_x2);
    cudaGetSymbolAddress((void**)&x3,  g_x3);

    // smem = Ws + hs + red
    const int smem0 = (H0 * 64 * 4 + 2 * H0 * 4) * 4 + 4 * 4 * 2 * 64 * 8;   //  83,968
    const int smem1 = (H1 * 64 * 4 + 2 * H1 * 4) * 4 + 4 * 4 * 2 * 64 * 8;   // 151,552
    const int smem2 = (H2 * 32 * 4 + 2 * H2 * 16) * 4 + 8 * 4 * 8 * 32 * 8;  // 229,376

    cudaFuncSetAttribute(lstm_recur_kernel<H0, 1, 4, 4>,
                         cudaFuncAttributeMaxDynamicSharedMemorySize, smem0);
    cudaFuncSetAttribute(lstm_recur_kernel<H1, 2, 4, 4>,
                         cudaFuncAttributeMaxDynamicSharedMemorySize, smem1);
    cudaFuncSetAttribute(lstm_recur_kernel<H2, 8, 16, 8>,
                         cudaFuncAttributeMaxDynamicSharedMemorySize, smem2);

    const int MBLK = (BATCH * SEQ) / 128;

    gemm_pre_kernel<INDIM, 4 * H0><<<dim3(MBLK, (4 * H0) / 64), 256>>>(noise, Wih0, bih0, bhh0, pre);
    lstm_recur_kernel<H0, 1, 4, 4><<<64, 256, smem0>>>(pre, Whh0, x1);

    gemm_pre_kernel<H0, 4 * H1><<<dim3(MBLK, (4 * H1) / 64), 256>>>(x1, Wih1, bih1, bhh1, pre);
    launch_cluster(lstm_recur_kernel<H1, 2, 4, 4>, 128, 2, smem1, pre, Whh1, x2);

    gemm_pre_kernel<H1, 4 * H2><<<dim3(MBLK, (4 * H2) / 64), 256>>>(x2, Wih2, bih2, bhh2, pre);
    launch_cluster(lstm_recur_kernel<H2, 8, 16, 8>, 128, 8, smem2, pre, Whh2, x3);

    final_kernel<<<(BATCH * SEQ) / 8, 256>>>(x3, Wl, bl, out);
}